// round 12
// baseline (speedup 1.0000x reference)
#include <cuda_runtime.h>
#include <cstdint>

// RNN forward, cluster-split persistent kernel. B=256, T=1024, IN=4, H=256.
// 64 clusters x 2 CTAs (128 CTAs, 256 thr each, 1/SM). Cluster = 4 batches.
// CTA rank r computes h rows [128r,128r+128) over all 256 k for 4 batches.
// Wh FULLY register-resident (64 u64 pairs/thread) -> zero weight smem traffic.
// Per-step h hand-off: st.shared::cluster to peer hbuf + per-thread
// release-arrive on peer mbar; only peer-half k-slice warps acquire-wait.

typedef unsigned long long u64;
#define T_LEN 1024

__device__ __forceinline__ u64 ffma2(u64 a, u64 b, u64 c) {
    u64 d;
    asm("fma.rn.f32x2 %0, %1, %2, %3;" : "=l"(d) : "l"(a), "l"(b), "l"(c));
    return d;
}
__device__ __forceinline__ float lo32(u64 v) { return __uint_as_float((unsigned)(v & 0xffffffffu)); }
__device__ __forceinline__ float hi32(u64 v) { return __uint_as_float((unsigned)(v >> 32)); }

__device__ __forceinline__ float fast_tanh(float x) {
    float a = fabsf(x);
    float e = __expf(2.0f * a);
    float r = 1.0f - __fdividef(2.0f, e + 1.0f);
    return copysignf(r, x);
}

__device__ __forceinline__ uint32_t s2u32(const void* p) {
    uint32_t a;
    asm("{ .reg .u64 t; cvta.to.shared.u64 t, %1; cvt.u32.u64 %0, t; }" : "=r"(a) : "l"(p));
    return a;
}

#define MBAR_INIT(addr, cnt) \
    asm volatile("mbarrier.init.shared.b64 [%0], %1;" :: "r"(addr), "r"(cnt) : "memory")

#define MBAR_ARRIVE_REMOTE(addr) \
    asm volatile("mbarrier.arrive.release.cluster.shared::cluster.b64 _, [%0];" :: "r"(addr) : "memory")

#define MBAR_WAIT_CLUSTER(_mbar, _par) do { \
    uint32_t _m = (_mbar); uint32_t _p = (_par); uint32_t _d; \
    asm volatile("{\n\t.reg .pred p;\n\t" \
      "mbarrier.try_wait.parity.acquire.cluster.shared::cta.b64 p, [%1], %2;\n\t" \
      "selp.b32 %0, 1, 0, p;\n\t}" : "=r"(_d) : "r"(_m), "r"(_p) : "memory"); \
    if (!_d) { \
      asm volatile("{\n\t.reg .pred P1;\n\t" \
        "WAITLP_%=:\n\t" \
        "mbarrier.try_wait.parity.acquire.cluster.shared::cta.b64 P1, [%0], %1, 0x989680;\n\t" \
        "@P1 bra.uni WAITDN_%=;\n\t" \
        "bra.uni WAITLP_%=;\n\t" \
        "WAITDN_%=:\n\t}" :: "r"(_m), "r"(_p) : "memory"); \
    } \
} while(0)

#define CLUSTER_SYNC() do { \
    asm volatile("barrier.cluster.arrive.aligned;" ::: "memory"); \
    asm volatile("barrier.cluster.wait.aligned;" ::: "memory"); \
} while(0)

__global__ void __launch_bounds__(256, 1) __cluster_dims__(2, 1, 1)
rnn_kernel(const float* __restrict__ x,        // [256][1024][4]
           const float* __restrict__ W_i2h,    // [256][260] (0..3 Wx, 4..259 Wh)
           const float* __restrict__ b_i2h,    // [256]
           const float* __restrict__ W_h2o,    // [256]
           const float* __restrict__ b_h2o,    // [1]
           const float* __restrict__ init_h,   // [256]
           float* __restrict__ out)            // [256]
{
    __shared__ __align__(16) float  hbuf[2][4][256];   // 8KB  [buf][batch][global row]
    __shared__ __align__(8)  float2 part2[8][128];     // 4KB  [kg*2+bp][local row]
    __shared__ __align__(16) float  xs[2][4][4];       // [buf][batch][4]
    __shared__ float scratch[8][2];
    __shared__ float halfs[4];
    __shared__ float peer_sums[4];
    __shared__ __align__(8) u64 mbar[1];

    const int t  = threadIdx.x;
    const int w  = t >> 5;
    const int l  = t & 31;
    const int kg = w & 3;                 // k in [64kg, 64kg+64)
    const int hg = (w >> 2) & 1;          // local rows [64hg, 64hg+64)
    const int kbase = kg * 64;

    uint32_t rank;
    asm("mov.u32 %0, %%cluster_ctarank;" : "=r"(rank));
    const int cid = blockIdx.x >> 1;
    const int b0g = cid * 4;              // 4 batches for this cluster

    const int rowL0 = hg * 64 + l;        // local rows computed by this thread
    const int rowL1 = rowL0 + 32;
    const int rowG0 = (int)rank * 128 + rowL0;
    const int rowG1 = (int)rank * 128 + rowL1;

    // ---- Wh: 64 u64 pairs, ALL in registers ----
    u64 wA[32], wB[32];
    {
        const ulonglong2* rpA = (const ulonglong2*)(W_i2h + (size_t)rowG0 * 260 + 4 + kbase);
        const ulonglong2* rpB = (const ulonglong2*)(W_i2h + (size_t)rowG1 * 260 + 4 + kbase);
        #pragma unroll
        for (int jj = 0; jj < 16; jj++) {
            ulonglong2 va = rpA[jj];
            wA[2*jj] = va.x; wA[2*jj + 1] = va.y;
            ulonglong2 vb = rpB[jj];
            wB[2*jj] = vb.x; wB[2*jj + 1] = vb.y;
        }
    }

    // reducer role: local row = t&127 (global = rank*128 + that), batch pair bp
    const int rrow = t & 127;
    const int bp   = t >> 7;              // batches {2bp, 2bp+1}
    const int rG   = (int)rank * 128 + rrow;
    const float4 wx = *(const float4*)(W_i2h + (size_t)rG * 260);
    const float bi = b_i2h[rG];
    const float wo = W_h2o[rG];

    // shared addresses (local + peer)
    const uint32_t mb_local = s2u32(mbar);
    const uint32_t hb_local = s2u32(&hbuf[0][0][0]);
    const uint32_t ps_local = s2u32(&peer_sums[0]);
    const uint32_t peer = rank ^ 1u;
    uint32_t mb_peer, hb_peer, ps_peer;
    asm("mapa.shared::cluster.u32 %0, %1, %2;" : "=r"(mb_peer) : "r"(mb_local), "r"(peer));
    asm("mapa.shared::cluster.u32 %0, %1, %2;" : "=r"(hb_peer) : "r"(hb_local), "r"(peer));
    asm("mapa.shared::cluster.u32 %0, %1, %2;" : "=r"(ps_peer) : "r"(ps_local), "r"(peer));

    if (t == 0) MBAR_INIT(mb_local, 256);
    __syncthreads();
    CLUSTER_SYNC();   // peer mbar init visible before any remote arrive

    // init h_0: each CTA fills ALL 256 rows locally (no exchange needed)
    {
        float hv = init_h[t];
        #pragma unroll
        for (int b = 0; b < 4; b++) hbuf[0][b][t] = hv;
    }
    if (t < 4) {
        float4 xv = *(const float4*)(x + ((size_t)(b0g + t) * T_LEN + 0) * 4);
        *(float4*)&xs[0][t][0] = xv;
    }
    __syncthreads();

    // warps whose k-slice lies in the peer's half must wait on peer's h
    const bool need_wait = ((uint32_t)(kg >> 1) != rank);

    float pool_e = 0.0f, pool_o = 0.0f;

    for (int step = 0; step < T_LEN; step++) {
        const int cur = step & 1;
        const int nxt = cur ^ 1;

        if (step > 0 && need_wait)
            MBAR_WAIT_CLUSTER(mb_local, (step - 1) & 1);

        // x prefetch for next step (threads 0..3)
        float4 xv;
        if (t < 4) {
            int tn = (step < T_LEN - 1) ? (step + 1) : step;
            xv = *(const float4*)(x + ((size_t)(b0g + t) * T_LEN + tn) * 4);
        }

        // xproj for reduce items (row rG, batches 2bp, 2bp+1)
        const float* xc0 = &xs[cur][2*bp][0];
        const float* xc1 = &xs[cur][2*bp + 1][0];
        float xpe = bi + wx.x*xc0[0] + wx.y*xc0[1] + wx.z*xc0[2] + wx.w*xc0[3];
        float xpo = bi + wx.x*xc1[0] + wx.y*xc1[1] + wx.z*xc1[2] + wx.w*xc1[3];

        // ---- FMA phase: 2 rows x 4 batches over this warp's 64-k slice ----
        const ulonglong2* hp0 = (const ulonglong2*)&hbuf[cur][0][kbase];
        const ulonglong2* hp1 = (const ulonglong2*)&hbuf[cur][1][kbase];
        const ulonglong2* hp2 = (const ulonglong2*)&hbuf[cur][2][kbase];
        const ulonglong2* hp3 = (const ulonglong2*)&hbuf[cur][3][kbase];

        u64 acc[2][4];
        #pragma unroll
        for (int r = 0; r < 2; r++)
            #pragma unroll
            for (int b = 0; b < 4; b++) acc[r][b] = 0ULL;

        #pragma unroll
        for (int jj = 0; jj < 16; jj++) {
            u64 wa = wA[2*jj], wb = wA[2*jj + 1];
            u64 va = wB[2*jj], vb = wB[2*jj + 1];
            ulonglong2 h0 = hp0[jj];
            ulonglong2 h1 = hp1[jj];
            ulonglong2 h2 = hp2[jj];
            ulonglong2 h3 = hp3[jj];
            acc[0][0] = ffma2(wa, h0.x, acc[0][0]); acc[0][0] = ffma2(wb, h0.y, acc[0][0]);
            acc[0][1] = ffma2(wa, h1.x, acc[0][1]); acc[0][1] = ffma2(wb, h1.y, acc[0][1]);
            acc[0][2] = ffma2(wa, h2.x, acc[0][2]); acc[0][2] = ffma2(wb, h2.y, acc[0][2]);
            acc[0][3] = ffma2(wa, h3.x, acc[0][3]); acc[0][3] = ffma2(wb, h3.y, acc[0][3]);
            acc[1][0] = ffma2(va, h0.x, acc[1][0]); acc[1][0] = ffma2(vb, h0.y, acc[1][0]);
            acc[1][1] = ffma2(va, h1.x, acc[1][1]); acc[1][1] = ffma2(vb, h1.y, acc[1][1]);
            acc[1][2] = ffma2(va, h2.x, acc[1][2]); acc[1][2] = ffma2(vb, h2.y, acc[1][2]);
            acc[1][3] = ffma2(va, h3.x, acc[1][3]); acc[1][3] = ffma2(vb, h3.y, acc[1][3]);
        }

        // partial stores: part2[kg*2 + bpair][local row] = {even batch, odd batch}
        part2[kg*2 + 0][rowL0] = make_float2(lo32(acc[0][0]) + hi32(acc[0][0]),
                                             lo32(acc[0][1]) + hi32(acc[0][1]));
        part2[kg*2 + 1][rowL0] = make_float2(lo32(acc[0][2]) + hi32(acc[0][2]),
                                             lo32(acc[0][3]) + hi32(acc[0][3]));
        part2[kg*2 + 0][rowL1] = make_float2(lo32(acc[1][0]) + hi32(acc[1][0]),
                                             lo32(acc[1][1]) + hi32(acc[1][1]));
        part2[kg*2 + 1][rowL1] = make_float2(lo32(acc[1][2]) + hi32(acc[1][2]),
                                             lo32(acc[1][3]) + hi32(acc[1][3]));
        __syncthreads();   // B1

        // ---- reduce 4 k-groups for (rrow, batches 2bp/2bp+1), tanh, pool ----
        float2 p0 = part2[0*2 + bp][rrow];
        float2 p1 = part2[1*2 + bp][rrow];
        float2 p2 = part2[2*2 + bp][rrow];
        float2 p3 = part2[3*2 + bp][rrow];
        float he = fast_tanh(xpe + ((p0.x + p1.x) + (p2.x + p3.x)));
        float ho = fast_tanh(xpo + ((p0.y + p1.y) + (p2.y + p3.y)));
        pool_e += he;
        pool_o += ho;

        // local h store (own half, global row rG)
        hbuf[nxt][2*bp][rG]     = he;
        hbuf[nxt][2*bp + 1][rG] = ho;

        // remote h store to peer + release-arrive (skip last step)
        if (step < T_LEN - 1) {
            uint32_t a0 = hb_peer + (uint32_t)(((nxt*4 + 2*bp) * 256 + rG) * 4);
            uint32_t a1 = hb_peer + (uint32_t)(((nxt*4 + 2*bp + 1) * 256 + rG) * 4);
            asm volatile("st.shared::cluster.f32 [%0], %1;" :: "r"(a0), "f"(he) : "memory");
            asm volatile("st.shared::cluster.f32 [%0], %1;" :: "r"(a1), "f"(ho) : "memory");
            MBAR_ARRIVE_REMOTE(mb_peer);
        }

        if (t < 4) *(float4*)&xs[nxt][t][0] = xv;
        __syncthreads();   // B2
    }

    // ---- output head: this CTA's half-sums for its 4 batches ----
    float ve = pool_e * wo;
    float vo = pool_o * wo;
    #pragma unroll
    for (int o = 16; o > 0; o >>= 1) {
        ve += __shfl_down_sync(0xffffffffu, ve, o);
        vo += __shfl_down_sync(0xffffffffu, vo, o);
    }
    if (l == 0) { scratch[w][0] = ve; scratch[w][1] = vo; }
    __syncthreads();
    if (t == 0) {
        halfs[0] = scratch[0][0] + scratch[1][0] + scratch[2][0] + scratch[3][0];
        halfs[1] = scratch[0][1] + scratch[1][1] + scratch[2][1] + scratch[3][1];
        halfs[2] = scratch[4][0] + scratch[5][0] + scratch[6][0] + scratch[7][0];
        halfs[3] = scratch[4][1] + scratch[5][1] + scratch[6][1] + scratch[7][1];
    }
    __syncthreads();
    CLUSTER_SYNC();                       // all remote hbuf traffic drained too
    if (rank == 1 && t < 4) {
        uint32_t a = ps_peer + (uint32_t)(t * 4);
        float v = halfs[t];
        asm volatile("st.shared::cluster.f32 [%0], %1;" :: "r"(a), "f"(v) : "memory");
    }
    CLUSTER_SYNC();
    if (rank == 0 && t < 4) {
        float bo = b_h2o[0];
        out[b0g + t] = (halfs[t] + peer_sums[t]) * (1.0f / 1024.0f) + bo;
    }
    CLUSTER_SYNC();                       // no CTA exits while peer may write
}

extern "C" void kernel_launch(void* const* d_in, const int* in_sizes, int n_in,
                              void* d_out, int out_size) {
    const float* x     = (const float*)d_in[0];
    const float* W_i2h = (const float*)d_in[1];
    const float* b_i2h = (const float*)d_in[2];
    const float* W_h2o = (const float*)d_in[3];
    const float* b_h2o = (const float*)d_in[4];
    const float* ih    = (const float*)d_in[5];
    float* outp = (float*)d_out;

    rnn_kernel<<<128, 256>>>(x, W_i2h, b_i2h, W_h2o, b_h2o, ih, outp);
}

// round 13
// speedup vs baseline: 1.5227x; 1.5227x over previous
#include <cuda_runtime.h>

// RNN forward, persistent dataflow-pipelined kernel. B=256, T=1024, H=256.
// 128 CTAs x 256 threads; CTA = 2 batches. kg = w>>1 (64-k slice), hg = w&1.
// NO __syncthreads in the step loop: 4 group barriers B_g (160 thr: the 4
// producer warps of h-group g + consumer pair g) + a 64-thr pair barrier for
// the h hand-off. Pairs drift; co-resident warps on an SMSP belong to
// different pairs, overlapping FMA with reduce/tanh/barrier-wait.
// part and hbuf parity double-buffered (drift < 2 steps by barrier chains).
// Wh: 86 u64-pairs/thread in regs + 21 ulonglong2/step streamed from smem.

typedef unsigned long long u64;
#define T_LEN 1024

__device__ __forceinline__ u64 ffma2(u64 a, u64 b, u64 c) {
    u64 d;
    asm("fma.rn.f32x2 %0, %1, %2, %3;" : "=l"(d) : "l"(a), "l"(b), "l"(c));
    return d;
}
__device__ __forceinline__ float lo32(u64 v) { return __uint_as_float((unsigned)(v & 0xffffffffu)); }
__device__ __forceinline__ float hi32(u64 v) { return __uint_as_float((unsigned)(v >> 32)); }

__device__ __forceinline__ float fast_tanh(float x) {
    float a = fabsf(x);
    float e = __expf(2.0f * a);
    float r = 1.0f - __fdividef(2.0f, e + 1.0f);
    return copysignf(r, x);
}

#define BAR_SYNC160(id)  asm volatile("bar.sync %0, 160;"   :: "r"(id) : "memory")
#define BAR_ARR160(id)   asm volatile("bar.arrive %0, 160;" :: "r"(id) : "memory")
#define BAR_SYNC64(id)   asm volatile("bar.sync %0, 64;"    :: "r"(id) : "memory")

// shared memory byte offsets
#define SM_WHS   0          // ulonglong2 WHS[8][21][32]      = 86016 B
#define SM_PART  86016      // float part[2][4][2][256]       = 16384 B
#define SM_HBUF  102400     // float hbuf[2][4][2][64]        = 4096 B
#define SM_SCR   106496     // float scratch[16]              = 64 B
#define SM_TOTAL 106560

__global__ void __launch_bounds__(256, 1)
rnn_kernel(const float* __restrict__ x,        // [256][1024][4]
           const float* __restrict__ W_i2h,    // [256][260] (0..3 Wx, 4..259 Wh)
           const float* __restrict__ b_i2h,    // [256]
           const float* __restrict__ W_h2o,    // [256]
           const float* __restrict__ b_h2o,    // [1]
           const float* __restrict__ init_h,   // [256]
           float* __restrict__ out)            // [256]
{
    extern __shared__ unsigned char sm[];
    ulonglong2* WHS = (ulonglong2*)(sm + SM_WHS);
    float* part = (float*)(sm + SM_PART);       // [par][kg'][b][256]
    float* hbuf = (float*)(sm + SM_HBUF);       // [par][kg][b][64]
    float* scratch = (float*)(sm + SM_SCR);

    const int t  = threadIdx.x;
    const int w  = t >> 5;
    const int l  = t & 31;
    const int kg = w >> 1;            // pair id; k-slice [64kg, 64kg+64)
    const int hg = w & 1;             // FMA rows [128hg, 128hg+128); batch role
    const int kbase = kg * 64;

    const int b0 = blockIdx.x * 2;
    const int h0r = hg * 128 + l;     // FMA rows: h0r + 32i, i = 0..3
    const int ga = 2 * hg;            // produced groups: ga (i=0,1), gb (i=2,3)
    const int gb = ga + 1;

    // ---- Wh: rows i0,i1 fully + row i2 pairs 0..21 in regs (86 pairs);
    //      i2 pairs 22..31 (5 ull2) + i3 (16 ull2) streamed: 21 ull2/thread ----
    u64 wreg[86];
    {
        #pragma unroll
        for (int i = 0; i < 2; i++) {
            const ulonglong2* rp = (const ulonglong2*)(W_i2h + (size_t)(h0r + i*32) * 260 + 4 + kbase);
            #pragma unroll
            for (int jj = 0; jj < 16; jj++) {
                ulonglong2 v = rp[jj];
                wreg[i*32 + 2*jj]     = v.x;
                wreg[i*32 + 2*jj + 1] = v.y;
            }
        }
        const ulonglong2* rp2 = (const ulonglong2*)(W_i2h + (size_t)(h0r + 2*32) * 260 + 4 + kbase);
        #pragma unroll
        for (int jj = 0; jj < 11; jj++) {
            ulonglong2 v = rp2[jj];
            wreg[64 + 2*jj]     = v.x;
            wreg[64 + 2*jj + 1] = v.y;
        }
        #pragma unroll
        for (int jj = 11; jj < 16; jj++)
            WHS[(w*21 + (jj - 11))*32 + l] = rp2[jj];
        const ulonglong2* rp3 = (const ulonglong2*)(W_i2h + (size_t)(h0r + 3*32) * 260 + 4 + kbase);
        #pragma unroll
        for (int jj = 0; jj < 16; jj++)
            WHS[(w*21 + 5 + jj)*32 + l] = rp3[jj];
    }

    // ---- reducer role: pair kg, batch hg, rows r0 = 64kg+l, r1 = r0+32 ----
    const int r0 = kbase + l;
    const int r1 = r0 + 32;
    const float4 wxA = *(const float4*)(W_i2h + (size_t)r0 * 260);
    const float4 wxB = *(const float4*)(W_i2h + (size_t)r1 * 260);
    const float biA = b_i2h[r0];
    const float biB = b_i2h[r1];
    const float* xb = x + (size_t)(b0 + hg) * T_LEN * 4;

    // prologue: pair fills its own h slice (both warps = both batches)
    hbuf[((0*4 + kg)*2 + hg)*64 + l]      = init_h[r0];
    hbuf[((0*4 + kg)*2 + hg)*64 + 32 + l] = init_h[r1];
    __syncthreads();

    float pool0 = 0.0f, pool1 = 0.0f;

    for (int step = 0; step < T_LEN; step++) {
        const int par = step & 1;
        const int nxt = par ^ 1;

        // x for this step (own batch), issued early; L1-resident after warmup
        float4 xv = __ldg((const float4*)(xb + (size_t)step * 4));

        // ---- FMA phase over this pair's k-slice, 4 rows x 2 batches ----
        const ulonglong2* hp0 = (const ulonglong2*)(hbuf + ((par*4 + kg)*2 + 0)*64);
        const ulonglong2* hp1 = (const ulonglong2*)(hbuf + ((par*4 + kg)*2 + 1)*64);

        u64 acc[4][2];
        #pragma unroll
        for (int i = 0; i < 4; i++) { acc[i][0] = 0ULL; acc[i][1] = 0ULL; }

        #pragma unroll
        for (int jj = 0; jj < 16; jj++) {
            ulonglong2 h0v = hp0[jj];
            ulonglong2 h1v = hp1[jj];
            #pragma unroll
            for (int i = 0; i < 2; i++) {
                u64 wa = wreg[i*32 + 2*jj];
                u64 wb = wreg[i*32 + 2*jj + 1];
                acc[i][0] = ffma2(wa, h0v.x, acc[i][0]);
                acc[i][0] = ffma2(wb, h0v.y, acc[i][0]);
                acc[i][1] = ffma2(wa, h1v.x, acc[i][1]);
                acc[i][1] = ffma2(wb, h1v.y, acc[i][1]);
            }
            u64 wa2, wb2;
            if (jj < 11) { wa2 = wreg[64 + 2*jj]; wb2 = wreg[64 + 2*jj + 1]; }
            else { ulonglong2 v = WHS[(w*21 + (jj - 11))*32 + l]; wa2 = v.x; wb2 = v.y; }
            acc[2][0] = ffma2(wa2, h0v.x, acc[2][0]);
            acc[2][0] = ffma2(wb2, h0v.y, acc[2][0]);
            acc[2][1] = ffma2(wa2, h1v.x, acc[2][1]);
            acc[2][1] = ffma2(wb2, h1v.y, acc[2][1]);
            ulonglong2 v3 = WHS[(w*21 + 5 + jj)*32 + l];
            acc[3][0] = ffma2(v3.x, h0v.x, acc[3][0]);
            acc[3][0] = ffma2(v3.y, h0v.y, acc[3][0]);
            acc[3][1] = ffma2(v3.x, h1v.x, acc[3][1]);
            acc[3][1] = ffma2(v3.y, h1v.y, acc[3][1]);
        }

        // ---- store partials group-ordered; arrive/sync group barriers ----
        float* pb = part + par*2048 + kg*512;    // [b][256]
        // group ga: rows i = 0, 1
        pb[0*256 + h0r]      = lo32(acc[0][0]) + hi32(acc[0][0]);
        pb[1*256 + h0r]      = lo32(acc[0][1]) + hi32(acc[0][1]);
        pb[0*256 + h0r + 32] = lo32(acc[1][0]) + hi32(acc[1][0]);
        pb[1*256 + h0r + 32] = lo32(acc[1][1]) + hi32(acc[1][1]);
        if (ga == kg) BAR_SYNC160(1 + ga); else BAR_ARR160(1 + ga);
        // group gb: rows i = 2, 3
        pb[0*256 + h0r + 64] = lo32(acc[2][0]) + hi32(acc[2][0]);
        pb[1*256 + h0r + 64] = lo32(acc[2][1]) + hi32(acc[2][1]);
        pb[0*256 + h0r + 96] = lo32(acc[3][0]) + hi32(acc[3][0]);
        pb[1*256 + h0r + 96] = lo32(acc[3][1]) + hi32(acc[3][1]);
        if (gb == kg) BAR_SYNC160(1 + gb); else BAR_ARR160(1 + gb);
        // consumer-only sync if this warp doesn't produce its own group
        if (kg != ga && kg != gb) BAR_SYNC160(1 + kg);

        // ---- reduce own group (rows r0, r1; batch hg) ----
        const float* pr = part + par*2048 + hg*256;
        float s0 = (pr[0*512 + r0] + pr[1*512 + r0]) +
                   (pr[2*512 + r0] + pr[3*512 + r0]);
        float s1 = (pr[0*512 + r1] + pr[1*512 + r1]) +
                   (pr[2*512 + r1] + pr[3*512 + r1]);
        float xp0 = biA + wxA.x*xv.x + wxA.y*xv.y + wxA.z*xv.z + wxA.w*xv.w;
        float xp1 = biB + wxB.x*xv.x + wxB.y*xv.y + wxB.z*xv.z + wxB.w*xv.w;
        float hn0 = fast_tanh(xp0 + s0);
        float hn1 = fast_tanh(xp1 + s1);
        pool0 += hn0;
        pool1 += hn1;
        hbuf[((nxt*4 + kg)*2 + hg)*64 + l]      = hn0;
        hbuf[((nxt*4 + kg)*2 + hg)*64 + 32 + l] = hn1;

        // pair barrier: both batches of this pair's h slice ready
        BAR_SYNC64(5 + kg);
    }

    __syncthreads();

    // ---- output head: out[b] = mean_t(h)[b] . W_h2o + b_h2o ----
    const float woA = W_h2o[r0];
    const float woB = W_h2o[r1];
    float v = pool0 * woA + pool1 * woB;      // this thread's batch = b0 + hg
    #pragma unroll
    for (int o = 16; o > 0; o >>= 1)
        v += __shfl_down_sync(0xffffffffu, v, o);
    if (l == 0) scratch[w] = v;
    __syncthreads();
    if (t == 0) {
        float s = (scratch[0] + scratch[2]) + (scratch[4] + scratch[6]);
        out[b0] = s * (1.0f / 1024.0f) + b_h2o[0];
    } else if (t == 1) {
        float s = (scratch[1] + scratch[3]) + (scratch[5] + scratch[7]);
        out[b0 + 1] = s * (1.0f / 1024.0f) + b_h2o[0];
    }
}

extern "C" void kernel_launch(void* const* d_in, const int* in_sizes, int n_in,
                              void* d_out, int out_size) {
    const float* x     = (const float*)d_in[0];
    const float* W_i2h = (const float*)d_in[1];
    const float* b_i2h = (const float*)d_in[2];
    const float* W_h2o = (const float*)d_in[3];
    const float* b_h2o = (const float*)d_in[4];
    const float* ih    = (const float*)d_in[5];
    float* outp = (float*)d_out;

    cudaFuncSetAttribute(rnn_kernel, cudaFuncAttributeMaxDynamicSharedMemorySize, SM_TOTAL);
    rnn_kernel<<<128, 256, SM_TOTAL>>>(x, W_i2h, b_i2h, W_h2o, b_h2o, ih, outp);
}

// round 15
// speedup vs baseline: 1.5942x; 1.0469x over previous
#include <cuda_runtime.h>

// RNN forward, fused persistent kernel. B=256, T=1024, IN=4, H=256, OUT=1.
// 128 CTAs x 256 threads; CTA = 2 batches for all 1024 steps.
// R15 = R11 champion (own-partial-in-regs, float2 partials, fast_tanh) with
// x read via direct per-thread __ldg (uniform-address broadcast, L1-resident)
// instead of 2-thread smem staging. No other changes.

typedef unsigned long long u64;

#define T_LEN   1024
#define KG_LEN  64

__device__ __forceinline__ u64 ffma2(u64 a, u64 b, u64 c) {
    u64 d;
    asm("fma.rn.f32x2 %0, %1, %2, %3;" : "=l"(d) : "l"(a), "l"(b), "l"(c));
    return d;
}
__device__ __forceinline__ float lo32(u64 v) { return __uint_as_float((unsigned)(v & 0xffffffffu)); }
__device__ __forceinline__ float hi32(u64 v) { return __uint_as_float((unsigned)(v >> 32)); }

__device__ __forceinline__ float fast_tanh(float x) {
    float a = fabsf(x);
    float e = __expf(2.0f * a);
    float r = 1.0f - __fdividef(2.0f, e + 1.0f);
    return copysignf(r, x);
}

// shared memory byte offsets
#define SM_WHS   0                  // ulonglong2 WHS[8][20][32]   = 81920 B
#define SM_HBUF  81920              // float hbuf[2][2][256]       = 4096 B
#define SM_PART  86016              // float2 part[4][256]         = 8192 B
#define SM_TOTAL 94208

__global__ void __launch_bounds__(256, 1)
rnn_kernel(const float* __restrict__ x,        // [256][1024][4]
           const float* __restrict__ W_i2h,    // [256][260]  (cols 0..3 = Wx, 4..259 = Wh)
           const float* __restrict__ b_i2h,    // [256]
           const float* __restrict__ W_h2o,    // [256]
           const float* __restrict__ b_h2o,    // [1]
           const float* __restrict__ init_h,   // [256]
           float* __restrict__ out)            // [256]
{
    extern __shared__ unsigned char sm[];
    ulonglong2* WHS = (ulonglong2*)(sm + SM_WHS);
    float* hbuf = (float*)(sm + SM_HBUF);
    float2* part2 = (float2*)(sm + SM_PART);    // part2[kg*256 + h] = {b0, b1}
    float* part = (float*)(sm + SM_PART);       // alias for head scratch
    const int t  = threadIdx.x;
    const int w  = t >> 5;
    const int l  = t & 31;
    const int kg = w & 3;             // k-group: k in [64*kg, 64*kg+64)
    const int hg = w >> 2;            // h-group: h in [128*hg, 128*hg+128)
    const int kbase = kg * KG_LEN;

    const int b0 = blockIdx.x * 2;
    const int h0r = hg * 128 + l;

    // permuted row assignment: row_i = h0r + 32*((i + kg) & 3); row_0 == t
    const int row1 = h0r + 32 * ((kg + 1) & 3);
    const int row2 = h0r + 32 * ((kg + 2) & 3);
    const int row3 = h0r + 32 * ((kg + 3) & 3);

    // ---- Wh: row0 (== t) and row1 fully + first 24 pairs of row2 in registers
    //      (88 pairs = 176 regs); rest of row2 + all of row3 in smem
    //      (20 ulonglong2 per thread = 80KB/CTA) ----
    u64 wreg[88];
    {
        const ulonglong2* rp0 = (const ulonglong2*)(W_i2h + (size_t)t * 260 + 4 + kbase);
        #pragma unroll
        for (int jj = 0; jj < 16; jj++) {
            ulonglong2 v = rp0[jj];
            wreg[2*jj]     = v.x;
            wreg[2*jj + 1] = v.y;
        }
        const ulonglong2* rp1 = (const ulonglong2*)(W_i2h + (size_t)row1 * 260 + 4 + kbase);
        #pragma unroll
        for (int jj = 0; jj < 16; jj++) {
            ulonglong2 v = rp1[jj];
            wreg[32 + 2*jj]     = v.x;
            wreg[32 + 2*jj + 1] = v.y;
        }
        const ulonglong2* rp2 = (const ulonglong2*)(W_i2h + (size_t)row2 * 260 + 4 + kbase);
        #pragma unroll
        for (int jj = 0; jj < 12; jj++) {
            ulonglong2 v = rp2[jj];
            wreg[64 + 2*jj]     = v.x;
            wreg[64 + 2*jj + 1] = v.y;
        }
        #pragma unroll
        for (int jj = 12; jj < 16; jj++)
            WHS[(w*20 + (jj - 12))*32 + l] = rp2[jj];
        const ulonglong2* rp3 = (const ulonglong2*)(W_i2h + (size_t)row3 * 260 + 4 + kbase);
        #pragma unroll
        for (int jj = 0; jj < 16; jj++)
            WHS[(w*20 + 4 + jj)*32 + l] = rp3[jj];
    }

    // reducer-role parameters for h = t
    const float4 wx = *(const float4*)(W_i2h + (size_t)t * 260);   // Wx[t][0..3]
    const float bi = b_i2h[t];
    const float* xb0 = x + (size_t)b0 * T_LEN * 4;
    const float* xb1 = x + (size_t)(b0 + 1) * T_LEN * 4;

    // init hidden state (buffer 0)
    {
        float hv = init_h[t];
        hbuf[0*512 + 0*256 + t] = hv;
        hbuf[0*512 + 1*256 + t] = hv;
    }
    __syncthreads();

    float pool0 = 0.0f, pool1 = 0.0f;
    int cur = 0;

    // tail load offsets for the 3 other k-groups (element index into part2)
    const int o1 = ((kg + 1) & 3) * 256 + t;
    const int o2 = ((kg + 2) & 3) * 256 + t;
    const int o3 = ((kg + 3) & 3) * 256 + t;

    for (int step = 0; step < T_LEN; step++) {
        const int nxt = cur ^ 1;

        // x for this step: uniform-address LDG (1 broadcast wf/warp, L1-hit
        // after first wave); xproj computed immediately -> 2-reg live range
        float4 xv0 = __ldg((const float4*)(xb0 + (size_t)step * 4));
        float4 xv1 = __ldg((const float4*)(xb1 + (size_t)step * 4));
        float xp0 = bi + wx.x*xv0.x + wx.y*xv0.y + wx.z*xv0.z + wx.w*xv0.w;
        float xp1 = bi + wx.x*xv1.x + wx.y*xv1.y + wx.z*xv1.z + wx.w*xv1.w;

        // ---- FMA phase: partial dot products over this warp's k range ----
        const ulonglong2* hp0 = (const ulonglong2*)(hbuf + cur*512 + 0*256 + kbase);
        const ulonglong2* hp1 = (const ulonglong2*)(hbuf + cur*512 + 1*256 + kbase);

        u64 acc[4][2];
        #pragma unroll
        for (int i = 0; i < 4; i++) { acc[i][0] = 0ULL; acc[i][1] = 0ULL; }

        #pragma unroll
        for (int jj = 0; jj < 16; jj++) {
            ulonglong2 h0v = hp0[jj];
            ulonglong2 h1v = hp1[jj];
            #pragma unroll
            for (int i = 0; i < 2; i++) {
                u64 wa = wreg[i*32 + 2*jj];
                u64 wb = wreg[i*32 + 2*jj + 1];
                acc[i][0] = ffma2(wa, h0v.x, acc[i][0]);
                acc[i][0] = ffma2(wb, h0v.y, acc[i][0]);
                acc[i][1] = ffma2(wa, h1v.x, acc[i][1]);
                acc[i][1] = ffma2(wb, h1v.y, acc[i][1]);
            }
            u64 wa2, wb2;
            if (jj < 12) { wa2 = wreg[64 + 2*jj]; wb2 = wreg[64 + 2*jj + 1]; }
            else { ulonglong2 v = WHS[(w*20 + (jj - 12))*32 + l]; wa2 = v.x; wb2 = v.y; }
            acc[2][0] = ffma2(wa2, h0v.x, acc[2][0]);
            acc[2][0] = ffma2(wb2, h0v.y, acc[2][0]);
            acc[2][1] = ffma2(wa2, h1v.x, acc[2][1]);
            acc[2][1] = ffma2(wb2, h1v.y, acc[2][1]);
            ulonglong2 v3 = WHS[(w*20 + 4 + jj)*32 + l];
            acc[3][0] = ffma2(v3.x, h0v.x, acc[3][0]);
            acc[3][0] = ffma2(v3.y, h0v.y, acc[3][0]);
            acc[3][1] = ffma2(v3.x, h1v.x, acc[3][1]);
            acc[3][1] = ffma2(v3.y, h1v.y, acc[3][1]);
        }

        // own partial (row_0 == t): keep in registers, skip store+load
        float s00 = lo32(acc[0][0]) + hi32(acc[0][0]);
        float s01 = lo32(acc[0][1]) + hi32(acc[0][1]);

        // store the 3 foreign partials: part2[kg*256 + row] = {b0, b1}
        {
            float2* pp = part2 + kg * 256;
            pp[row1] = make_float2(lo32(acc[1][0]) + hi32(acc[1][0]),
                                   lo32(acc[1][1]) + hi32(acc[1][1]));
            pp[row2] = make_float2(lo32(acc[2][0]) + hi32(acc[2][0]),
                                   lo32(acc[2][1]) + hi32(acc[2][1]));
            pp[row3] = make_float2(lo32(acc[3][0]) + hi32(acc[3][0]),
                                   lo32(acc[3][1]) + hi32(acc[3][1]));
        }
        __syncthreads();

        // ---- tail: reduce 3 foreign partials + own, tanh, pool, store state ----
        float2 pa = part2[o1];
        float2 pb = part2[o2];
        float2 pc = part2[o3];
        float r0 = s00 + ((pa.x + pb.x) + pc.x);
        float r1 = s01 + ((pa.y + pb.y) + pc.y);
        float hn0 = fast_tanh(xp0 + r0);
        float hn1 = fast_tanh(xp1 + r1);
        pool0 += hn0;
        pool1 += hn1;
        hbuf[nxt*512 + 0*256 + t] = hn0;
        hbuf[nxt*512 + 1*256 + t] = hn1;
        __syncthreads();
        cur = nxt;
    }

    // ---- output head: out[b] = mean_t(h)[b] . W_h2o + b_h2o ----
    const float wo = W_h2o[t];
    const float bo = b_h2o[0];
    float v0 = pool0 * (1.0f / 1024.0f) * wo;
    float v1 = pool1 * (1.0f / 1024.0f) * wo;
    #pragma unroll
    for (int o = 16; o > 0; o >>= 1) {
        v0 += __shfl_down_sync(0xffffffffu, v0, o);
        v1 += __shfl_down_sync(0xffffffffu, v1, o);
    }
    if (l == 0) { part[w] = v0; part[8 + w] = v1; }
    __syncthreads();
    if (t == 0) {
        float s = 0.0f;
        #pragma unroll
        for (int i = 0; i < 8; i++) s += part[i];
        out[b0] = s + bo;
    } else if (t == 1) {
        float s = 0.0f;
        #pragma unroll
        for (int i = 0; i < 8; i++) s += part[8 + i];
        out[b0 + 1] = s + bo;
    }
}

extern "C" void kernel_launch(void* const* d_in, const int* in_sizes, int n_in,
                              void* d_out, int out_size) {
    const float* x     = (const float*)d_in[0];
    const float* W_i2h = (const float*)d_in[1];
    const float* b_i2h = (const float*)d_in[2];
    const float* W_h2o = (const float*)d_in[3];
    const float* b_h2o = (const float*)d_in[4];
    const float* ih    = (const float*)d_in[5];
    float* outp = (float*)d_out;

    cudaFuncSetAttribute(rnn_kernel, cudaFuncAttributeMaxDynamicSharedMemorySize, SM_TOTAL);
    rnn_kernel<<<128, 256, SM_TOTAL>>>(x, W_i2h, b_i2h, W_h2o, b_h2o, ih, outp);
}

// round 16
// speedup vs baseline: 1.6301x; 1.0226x over previous
#include <cuda_runtime.h>

// RNN forward, fused persistent kernel. B=256, T=1024, IN=4, H=256, OUT=1.
// 128 CTAs x 256 threads; CTA = 2 batches for all 1024 steps.
// FINAL (= R11 champion, 965us): FFMA2 inner product; Wh 88 u64-pairs/thread
// in registers + 20 ulonglong2/step streamed from smem; accumulator rows
// permuted so each thread's own partial (h = threadIdx) stays in registers;
// float2 partial layout (STS.64/LDS.64); branchless fast_tanh; x staged to
// smem by 2 threads, double-buffered.

typedef unsigned long long u64;

#define T_LEN   1024
#define KG_LEN  64

__device__ __forceinline__ u64 ffma2(u64 a, u64 b, u64 c) {
    u64 d;
    asm("fma.rn.f32x2 %0, %1, %2, %3;" : "=l"(d) : "l"(a), "l"(b), "l"(c));
    return d;
}
__device__ __forceinline__ float lo32(u64 v) { return __uint_as_float((unsigned)(v & 0xffffffffu)); }
__device__ __forceinline__ float hi32(u64 v) { return __uint_as_float((unsigned)(v >> 32)); }

__device__ __forceinline__ float fast_tanh(float x) {
    float a = fabsf(x);
    float e = __expf(2.0f * a);
    float r = 1.0f - __fdividef(2.0f, e + 1.0f);
    return copysignf(r, x);
}

// shared memory byte offsets
#define SM_WHS   0                  // ulonglong2 WHS[8][20][32]   = 81920 B
#define SM_HBUF  81920              // float hbuf[2][2][256]       = 4096 B
#define SM_PART  86016              // float2 part[4][256]         = 8192 B
#define SM_XS    94208              // float xs[2][8]              = 64 B
#define SM_TOTAL 94272

__global__ void __launch_bounds__(256, 1)
rnn_kernel(const float* __restrict__ x,        // [256][1024][4]
           const float* __restrict__ W_i2h,    // [256][260]  (cols 0..3 = Wx, 4..259 = Wh)
           const float* __restrict__ b_i2h,    // [256]
           const float* __restrict__ W_h2o,    // [256]
           const float* __restrict__ b_h2o,    // [1]
           const float* __restrict__ init_h,   // [256]
           float* __restrict__ out)            // [256]
{
    extern __shared__ unsigned char sm[];
    ulonglong2* WHS = (ulonglong2*)(sm + SM_WHS);
    float* hbuf = (float*)(sm + SM_HBUF);
    float2* part2 = (float2*)(sm + SM_PART);    // part2[kg*256 + h] = {b0, b1}
    float* part = (float*)(sm + SM_PART);       // alias for head scratch
    float* xs   = (float*)(sm + SM_XS);

    const int t  = threadIdx.x;
    const int w  = t >> 5;
    const int l  = t & 31;
    const int kg = w & 3;             // k-group: k in [64*kg, 64*kg+64)
    const int hg = w >> 2;            // h-group: h in [128*hg, 128*hg+128)
    const int kbase = kg * KG_LEN;

    const int b0 = blockIdx.x * 2;
    const int h0r = hg * 128 + l;

    // permuted row assignment: row_i = h0r + 32*((i + kg) & 3); row_0 == t
    const int row1 = h0r + 32 * ((kg + 1) & 3);
    const int row2 = h0r + 32 * ((kg + 2) & 3);
    const int row3 = h0r + 32 * ((kg + 3) & 3);

    // ---- Wh: row0 (== t) and row1 fully + first 24 pairs of row2 in registers
    //      (88 pairs = 176 regs); rest of row2 + all of row3 in smem
    //      (20 ulonglong2 per thread = 80KB/CTA) ----
    u64 wreg[88];
    {
        const ulonglong2* rp0 = (const ulonglong2*)(W_i2h + (size_t)t * 260 + 4 + kbase);
        #pragma unroll
        for (int jj = 0; jj < 16; jj++) {
            ulonglong2 v = rp0[jj];
            wreg[2*jj]     = v.x;
            wreg[2*jj + 1] = v.y;
        }
        const ulonglong2* rp1 = (const ulonglong2*)(W_i2h + (size_t)row1 * 260 + 4 + kbase);
        #pragma unroll
        for (int jj = 0; jj < 16; jj++) {
            ulonglong2 v = rp1[jj];
            wreg[32 + 2*jj]     = v.x;
            wreg[32 + 2*jj + 1] = v.y;
        }
        const ulonglong2* rp2 = (const ulonglong2*)(W_i2h + (size_t)row2 * 260 + 4 + kbase);
        #pragma unroll
        for (int jj = 0; jj < 12; jj++) {
            ulonglong2 v = rp2[jj];
            wreg[64 + 2*jj]     = v.x;
            wreg[64 + 2*jj + 1] = v.y;
        }
        #pragma unroll
        for (int jj = 12; jj < 16; jj++)
            WHS[(w*20 + (jj - 12))*32 + l] = rp2[jj];
        const ulonglong2* rp3 = (const ulonglong2*)(W_i2h + (size_t)row3 * 260 + 4 + kbase);
        #pragma unroll
        for (int jj = 0; jj < 16; jj++)
            WHS[(w*20 + 4 + jj)*32 + l] = rp3[jj];
    }

    // reducer-role parameters for h = t
    const float4 wx = *(const float4*)(W_i2h + (size_t)t * 260);   // Wx[t][0..3]
    const float bi = b_i2h[t];
    const float wo = W_h2o[t];
    const float bo = b_h2o[0];

    // init hidden state (buffer 0) and x for step 0
    {
        float hv = init_h[t];
        hbuf[0*512 + 0*256 + t] = hv;
        hbuf[0*512 + 1*256 + t] = hv;
        if (t < 2) {
            float4 xv = *(const float4*)(x + ((size_t)(b0 + t) * T_LEN + 0) * 4);
            *(float4*)(xs + t*4) = xv;
        }
    }
    __syncthreads();

    float pool0 = 0.0f, pool1 = 0.0f;
    int cur = 0;

    // tail load offsets for the 3 other k-groups (element index into part2)
    const int o1 = ((kg + 1) & 3) * 256 + t;
    const int o2 = ((kg + 2) & 3) * 256 + t;
    const int o3 = ((kg + 3) & 3) * 256 + t;

    for (int step = 0; step < T_LEN; step++) {
        const int nxt = cur ^ 1;

        // prefetch x for next step (threads 0,1)
        float4 xv;
        if (t < 2) {
            int tn = (step < T_LEN - 1) ? (step + 1) : step;
            xv = *(const float4*)(x + ((size_t)(b0 + t) * T_LEN + tn) * 4);
        }

        // xproj for h = t
        const float* xsc = xs + cur*8;
        float xp0 = bi + wx.x*xsc[0] + wx.y*xsc[1] + wx.z*xsc[2] + wx.w*xsc[3];
        float xp1 = bi + wx.x*xsc[4] + wx.y*xsc[5] + wx.z*xsc[6] + wx.w*xsc[7];

        // ---- FMA phase: partial dot products over this warp's k range ----
        const ulonglong2* hp0 = (const ulonglong2*)(hbuf + cur*512 + 0*256 + kbase);
        const ulonglong2* hp1 = (const ulonglong2*)(hbuf + cur*512 + 1*256 + kbase);

        u64 acc[4][2];
        #pragma unroll
        for (int i = 0; i < 4; i++) { acc[i][0] = 0ULL; acc[i][1] = 0ULL; }

        #pragma unroll
        for (int jj = 0; jj < 16; jj++) {
            ulonglong2 h0v = hp0[jj];
            ulonglong2 h1v = hp1[jj];
            #pragma unroll
            for (int i = 0; i < 2; i++) {
                u64 wa = wreg[i*32 + 2*jj];
                u64 wb = wreg[i*32 + 2*jj + 1];
                acc[i][0] = ffma2(wa, h0v.x, acc[i][0]);
                acc[i][0] = ffma2(wb, h0v.y, acc[i][0]);
                acc[i][1] = ffma2(wa, h1v.x, acc[i][1]);
                acc[i][1] = ffma2(wb, h1v.y, acc[i][1]);
            }
            u64 wa2, wb2;
            if (jj < 12) { wa2 = wreg[64 + 2*jj]; wb2 = wreg[64 + 2*jj + 1]; }
            else { ulonglong2 v = WHS[(w*20 + (jj - 12))*32 + l]; wa2 = v.x; wb2 = v.y; }
            acc[2][0] = ffma2(wa2, h0v.x, acc[2][0]);
            acc[2][0] = ffma2(wb2, h0v.y, acc[2][0]);
            acc[2][1] = ffma2(wa2, h1v.x, acc[2][1]);
            acc[2][1] = ffma2(wb2, h1v.y, acc[2][1]);
            ulonglong2 v3 = WHS[(w*20 + 4 + jj)*32 + l];
            acc[3][0] = ffma2(v3.x, h0v.x, acc[3][0]);
            acc[3][0] = ffma2(v3.y, h0v.y, acc[3][0]);
            acc[3][1] = ffma2(v3.x, h1v.x, acc[3][1]);
            acc[3][1] = ffma2(v3.y, h1v.y, acc[3][1]);
        }

        // own partial (row_0 == t): keep in registers, skip store+load
        float s00 = lo32(acc[0][0]) + hi32(acc[0][0]);
        float s01 = lo32(acc[0][1]) + hi32(acc[0][1]);

        // store the 3 foreign partials: part2[kg*256 + row] = {b0, b1}
        {
            float2* pp = part2 + kg * 256;
            pp[row1] = make_float2(lo32(acc[1][0]) + hi32(acc[1][0]),
                                   lo32(acc[1][1]) + hi32(acc[1][1]));
            pp[row2] = make_float2(lo32(acc[2][0]) + hi32(acc[2][0]),
                                   lo32(acc[2][1]) + hi32(acc[2][1]));
            pp[row3] = make_float2(lo32(acc[3][0]) + hi32(acc[3][0]),
                                   lo32(acc[3][1]) + hi32(acc[3][1]));
        }
        __syncthreads();

        // ---- tail: reduce 3 foreign partials + own, tanh, pool, store state ----
        float2 pa = part2[o1];
        float2 pb = part2[o2];
        float2 pc = part2[o3];
        float r0 = s00 + ((pa.x + pb.x) + pc.x);
        float r1 = s01 + ((pa.y + pb.y) + pc.y);
        float hn0 = fast_tanh(xp0 + r0);
        float hn1 = fast_tanh(xp1 + r1);
        pool0 += hn0;
        pool1 += hn1;
        hbuf[nxt*512 + 0*256 + t] = hn0;
        hbuf[nxt*512 + 1*256 + t] = hn1;
        if (t < 2) *(float4*)(xs + nxt*8 + t*4) = xv;
        __syncthreads();
        cur = nxt;
    }

    // ---- output head: out[b] = mean_t(h)[b] . W_h2o + b_h2o ----
    float v0 = pool0 * (1.0f / 1024.0f) * wo;
    float v1 = pool1 * (1.0f / 1024.0f) * wo;
    #pragma unroll
    for (int o = 16; o > 0; o >>= 1) {
        v0 += __shfl_down_sync(0xffffffffu, v0, o);
        v1 += __shfl_down_sync(0xffffffffu, v1, o);
    }
    if (l == 0) { part[w] = v0; part[8 + w] = v1; }
    __syncthreads();
    if (t == 0) {
        float s = 0.0f;
        #pragma unroll
        for (int i = 0; i < 8; i++) s += part[i];
        out[b0] = s + bo;
    } else if (t == 1) {
        float s = 0.0f;
        #pragma unroll
        for (int i = 0; i < 8; i++) s += part[8 + i];
        out[b0 + 1] = s + bo;
    }
}

extern "C" void kernel_launch(void* const* d_in, const int* in_sizes, int n_in,
                              void* d_out, int out_size) {
    const float* x     = (const float*)d_in[0];
    const float* W_i2h = (const float*)d_in[1];
    const float* b_i2h = (const float*)d_in[2];
    const float* W_h2o = (const float*)d_in[3];
    const float* b_h2o = (const float*)d_in[4];
    const float* ih    = (const float*)d_in[5];
    float* outp = (float*)d_out;

    cudaFuncSetAttribute(rnn_kernel, cudaFuncAttributeMaxDynamicSharedMemorySize, SM_TOTAL);
    rnn_kernel<<<128, 256, SM_TOTAL>>>(x, W_i2h, b_i2h, W_h2o, b_h2o, ih, outp);
}